// round 1
// baseline (speedup 1.0000x reference)
#include <cuda_runtime.h>
#include <cstdint>

// ---------------------------------------------------------------------------
// Problem constants
//   x  [1024,4096]  Wq [4096,16384]  bq[16384]  Wk [4096,16384]  bk[16384]
//   v  [256,4096]   Wl [4096,4096]   bl[4096]   out [1024,4096] fp32
// ---------------------------------------------------------------------------
#define B_SZ   1024
#define FIN    4096
#define NMEM   256
#define SQF    64
#define QKN    (NMEM * SQF)   // 16384

// Scratch (no allocation allowed -> __device__ globals)
__device__ float g_tmp[B_SZ * QKN];     // 64 MB: holds relu(xq) then relu(xk)
__device__ float g_qsum[B_SZ * SQF];    // 256 KB
__device__ float g_savg[B_SZ * NMEM];   // 1 MB
__device__ float g_pooled[B_SZ * FIN];  // 16 MB

// ---------------------------------------------------------------------------
// SGEMM: C = (A @ B) [+ bias] [+ res], optional relu.
// A row-major [M,K], B row-major [K,N]. 128x128 block tile, BK=8, 8x8/thread.
// Requires M%128==0, N%128==0, K%8==0 (all shapes here satisfy this).
// ---------------------------------------------------------------------------
template<bool RELU, bool BIAS, bool RES>
__global__ __launch_bounds__(256, 2)
void sgemm128(const float* __restrict__ A, const float* __restrict__ B,
              const float* __restrict__ bias, const float* __restrict__ res,
              float* __restrict__ C, int M, int N, int K)
{
    __shared__ float As[2][8][128];
    __shared__ float Bs[2][8][128];

    const int bm0 = blockIdx.y * 128;
    const int bn0 = blockIdx.x * 128;
    const int tid = threadIdx.x;
    const int tx  = tid & 15;        // 0..15  (N direction)
    const int ty  = tid >> 4;        // 0..15  (M direction)

    // A-loader: 128 rows x 8 k's = 1024 floats, float4 each
    const int arow = tid >> 1;             // 0..127
    const int acol = (tid & 1) * 4;        // 0 or 4
    // B-loader: 8 k-rows x 128 cols
    const int brow = tid >> 5;             // 0..7
    const int bcol = (tid & 31) * 4;       // 0..124

    const float* Aptr = A + (size_t)(bm0 + arow) * K + acol;
    const float* Bptr = B + (size_t)brow * N + bn0 + bcol;

    float4 a4 = *(const float4*)Aptr;
    float4 b4 = *(const float4*)Bptr;
    As[0][acol + 0][arow] = a4.x;
    As[0][acol + 1][arow] = a4.y;
    As[0][acol + 2][arow] = a4.z;
    As[0][acol + 3][arow] = a4.w;
    *(float4*)&Bs[0][brow][bcol] = b4;
    __syncthreads();

    float acc[8][8];
    #pragma unroll
    for (int i = 0; i < 8; i++)
        #pragma unroll
        for (int j = 0; j < 8; j++) acc[i][j] = 0.f;

    const int nk = K >> 3;
    for (int kt = 0; kt < nk; kt++) {
        const int buf = kt & 1;
        if (kt + 1 < nk) {
            a4 = *(const float4*)(Aptr + (size_t)(kt + 1) * 8);
            b4 = *(const float4*)(Bptr + (size_t)(kt + 1) * 8 * N);
        }
        #pragma unroll
        for (int k = 0; k < 8; k++) {
            float ra[8], rb[8];
            *(float4*)&ra[0] = *(const float4*)&As[buf][k][ty * 8];
            *(float4*)&ra[4] = *(const float4*)&As[buf][k][ty * 8 + 4];
            *(float4*)&rb[0] = *(const float4*)&Bs[buf][k][tx * 8];
            *(float4*)&rb[4] = *(const float4*)&Bs[buf][k][tx * 8 + 4];
            #pragma unroll
            for (int i = 0; i < 8; i++)
                #pragma unroll
                for (int j = 0; j < 8; j++)
                    acc[i][j] = fmaf(ra[i], rb[j], acc[i][j]);
        }
        if (kt + 1 < nk) {
            const int nb = buf ^ 1;
            As[nb][acol + 0][arow] = a4.x;
            As[nb][acol + 1][arow] = a4.y;
            As[nb][acol + 2][arow] = a4.z;
            As[nb][acol + 3][arow] = a4.w;
            *(float4*)&Bs[nb][brow][bcol] = b4;
        }
        __syncthreads();
    }

    // Epilogue
    #pragma unroll
    for (int i = 0; i < 8; i++) {
        const int row = bm0 + ty * 8 + i;
        #pragma unroll
        for (int j = 0; j < 8; j += 4) {
            const int col = bn0 + tx * 8 + j;
            float4 o;
            o.x = acc[i][j + 0];
            o.y = acc[i][j + 1];
            o.z = acc[i][j + 2];
            o.w = acc[i][j + 3];
            if (BIAS) {
                const float4 bb = *(const float4*)&bias[col];
                o.x += bb.x; o.y += bb.y; o.z += bb.z; o.w += bb.w;
            }
            if (RES) {
                const float4 rr = *(const float4*)&res[(size_t)row * N + col];
                o.x += rr.x; o.y += rr.y; o.z += rr.z; o.w += rr.w;
            }
            if (RELU) {
                o.x = fmaxf(o.x, 0.f); o.y = fmaxf(o.y, 0.f);
                o.z = fmaxf(o.z, 0.f); o.w = fmaxf(o.w, 0.f);
            }
            *(float4*)&C[(size_t)row * N + col] = o;
        }
    }
}

// ---------------------------------------------------------------------------
// q_sum[b,s] = sum_{m<256} g_tmp[b, m*64 + s]   (g_tmp holds relu(xq))
// grid=1024, block=256
// ---------------------------------------------------------------------------
__global__ void qsum_kernel()
{
    const int b = blockIdx.x;
    const int t = threadIdx.x;
    const int s = t & 63;
    const int g = t >> 6;   // 0..3
    const float* base = g_tmp + (size_t)b * QKN;
    float sum = 0.f;
    #pragma unroll 4
    for (int m = g; m < NMEM; m += 4) sum += base[m * SQF + s];
    __shared__ float sh[4][64];
    sh[g][s] = sum;
    __syncthreads();
    if (g == 0)
        g_qsum[b * SQF + s] = sh[0][s] + sh[1][s] + sh[2][s] + sh[3][s];
}

// ---------------------------------------------------------------------------
// s_avg[b,n] = (1/(256*8)) * sum_s g_tmp[b, n*64+s] * q_sum[b,s]
//  (g_tmp now holds relu(xk)). grid=1024, block=256 (8 warps, warp per n-slice)
// ---------------------------------------------------------------------------
__global__ void savg_kernel()
{
    const int b = blockIdx.x;
    const int t = threadIdx.x;
    const int lane = t & 31;
    const int w = t >> 5;   // 0..7
    __shared__ float q[64];
    if (t < 64) q[t] = g_qsum[b * SQF + t];
    __syncthreads();
    const float* base = g_tmp + (size_t)b * QKN;
    const float inv = 1.0f / (256.0f * 8.0f);
    for (int n = w; n < NMEM; n += 8) {
        float sum = base[n * SQF + lane] * q[lane]
                  + base[n * SQF + 32 + lane] * q[32 + lane];
        #pragma unroll
        for (int off = 16; off; off >>= 1)
            sum += __shfl_xor_sync(0xffffffffu, sum, off);
        if (lane == 0) g_savg[b * NMEM + n] = sum * inv;
    }
}

// ---------------------------------------------------------------------------
extern "C" void kernel_launch(void* const* d_in, const int* in_sizes, int n_in,
                              void* d_out, int out_size)
{
    const float* x  = (const float*)d_in[0];
    const float* Wq = (const float*)d_in[1];
    const float* bq = (const float*)d_in[2];
    const float* Wk = (const float*)d_in[3];
    const float* bk = (const float*)d_in[4];
    const float* v  = (const float*)d_in[5];
    const float* Wl = (const float*)d_in[6];
    const float* bl = (const float*)d_in[7];
    float* out = (float*)d_out;

    float *tmp, *savg, *pooled;
    cudaGetSymbolAddress((void**)&tmp,    g_tmp);
    cudaGetSymbolAddress((void**)&savg,   g_savg);
    cudaGetSymbolAddress((void**)&pooled, g_pooled);

    // 1) relu(x @ Wq + bq) -> tmp   [1024,16384]
    {
        dim3 grid(QKN / 128, B_SZ / 128);
        sgemm128<true, true, false><<<grid, 256>>>(x, Wq, bq, nullptr, tmp,
                                                   B_SZ, QKN, FIN);
    }
    // 2) q_sum
    qsum_kernel<<<B_SZ, 256>>>();
    // 3) relu(x @ Wk + bk) -> tmp   [1024,16384]
    {
        dim3 grid(QKN / 128, B_SZ / 128);
        sgemm128<true, true, false><<<grid, 256>>>(x, Wk, bk, nullptr, tmp,
                                                   B_SZ, QKN, FIN);
    }
    // 4) s_avg
    savg_kernel<<<B_SZ, 256>>>();
    // 5) pooled = s_avg @ v   [1024,256]@[256,4096]
    {
        dim3 grid(FIN / 128, B_SZ / 128);
        sgemm128<false, false, false><<<grid, 256>>>(savg, v, nullptr, nullptr,
                                                     pooled, B_SZ, FIN, NMEM);
    }
    // 6) out = x + pooled @ Wl + bl
    {
        dim3 grid(FIN / 128, B_SZ / 128);
        sgemm128<false, true, true><<<grid, 256>>>(pooled, Wl, bl, x, out,
                                                   B_SZ, FIN, FIN);
    }
}